// round 17
// baseline (speedup 1.0000x reference)
#include <cuda_runtime.h>
#include <math.h>

#define CC 256
#define HH 64
#define NPIX (HH*HH)
typedef unsigned long long u64;

#define OFF2   (CC*NPIX)
#define OFF4   (CC*NPIX + CC*1024)
#define TOTPIX (NPIX + 1024 + 256)
#define QOFF2  (3*CC*NPIX)
#define QOFF4  (3*CC*NPIX + 3*CC*1024)

// ---------------- packed f32x2 helpers ----------------
__device__ __forceinline__ void ffma2(u64 &d, u64 a, u64 b) {
    asm("fma.rn.f32x2 %0, %1, %2, %0;" : "+l"(d) : "l"(a), "l"(b));
}
__device__ __forceinline__ u64 pack2(float lo, float hi) {
    u64 r; asm("mov.b64 %0, {%1, %2};" : "=l"(r) : "f"(lo), "f"(hi)); return r;
}
__device__ __forceinline__ float2 unpack2(u64 v) {
    float2 r; asm("mov.b64 {%0, %1}, %2;" : "=f"(r.x), "=f"(r.y) : "l"(v)); return r;
}

// ---------------- scratch ----------------
__device__ float g_xs [CC*(1024+256)];
__device__ float g_dw [CC*TOTPIX];
__device__ float g_pos[CC*TOTPIX];
__device__ float g_qkv[3*CC*TOTPIX];
__device__ float g_att[CC*(1024+256)];
__device__ float g_cat[3*CC*NPIX];

// ---------------- avg pool, both scales ----------------
__global__ void pool_all_kernel(const float* __restrict__ x,
                                float* __restrict__ xs2, float* __restrict__ xs4) {
    int b = blockIdx.x;
    int s, Hs, idx; float* out;
    if (b < 1024) { s = 2; Hs = 32; out = xs2; idx = b * 256 + threadIdx.x; }
    else          { s = 4; Hs = 16; out = xs4; idx = (b - 1024) * 256 + threadIdx.x; }
    int xo = idx % Hs, yo = (idx / Hs) % Hs, c = idx / (Hs * Hs);
    const float* xp = x + c * NPIX + (yo * s) * HH + xo * s;
    float sum = 0.f;
    for (int dy = 0; dy < s; dy++)
        for (int dx = 0; dx < s; dx++) sum += xp[dy * HH + dx];
    out[idx] = sum * (1.0f / (s * s));
}

// ---------------- fused depthwise 3x3 (dw + pos), all scales ----------------
__global__ void dwconv_all_kernel(const float* __restrict__ x,
                                  const float* __restrict__ xs2, const float* __restrict__ xs4,
                                  const float* __restrict__ dw_w, const float* __restrict__ dw_b,
                                  const float* __restrict__ pos_w, const float* __restrict__ pos_b,
                                  float* __restrict__ dwout, float* __restrict__ posout) {
    int b = blockIdx.x;
    int i, Hs, off, bl; const float* src;
    if (b < 4096)      { i = 0; Hs = 64; src = x;   off = 0;    bl = b; }
    else if (b < 5120) { i = 1; Hs = 32; src = xs2; off = OFF2; bl = b - 4096; }
    else               { i = 2; Hs = 16; src = xs4; off = OFF4; bl = b - 5120; }
    int idx = bl * 256 + threadIdx.x;
    int x0 = idx % Hs, y0 = (idx / Hs) % Hs, c = idx / (Hs * Hs);
    const float* xp = src + c * Hs * Hs;
    const float* wd = dw_w + i * CC * 9 + c * 9;
    const float* wp = pos_w + i * CC * 9 + c * 9;
    float a = dw_b[i * CC + c], p = pos_b[i * CC + c];
#pragma unroll
    for (int ky = 0; ky < 3; ky++) {
        int y = y0 + ky - 1;
        if ((unsigned)y >= (unsigned)Hs) continue;
#pragma unroll
        for (int kx = 0; kx < 3; kx++) {
            int xx = x0 + kx - 1;
            if ((unsigned)xx >= (unsigned)Hs) continue;
            float v = __ldg(xp + y * Hs + xx);
            a = fmaf(v, wd[ky * 3 + kx], a);
            p = fmaf(v, wp[ky * 3 + kx], p);
        }
    }
    dwout[off + idx]  = a;
    posout[off + idx] = p;
}

// ---------------- 128x128 GEMM tile, 8x8 micro, FFMA2 (pairs along m) ----------------
template <bool ADD_POS>
__device__ __forceinline__ void gemm_tile128(const float* __restrict__ W, const float* __restrict__ A,
                                             const float* __restrict__ bias, const float* __restrict__ pos,
                                             float* __restrict__ Cout, int Kd, int N, int m0, int n0) {
    __shared__ __align__(16) float Wt[16][132];   // [k][m]
    __shared__ __align__(16) float As[16][132];   // [k][n]
    int tid = threadIdx.x;
    int tm = tid >> 4, tn = tid & 15;
    int wm = tid >> 2, wk = (tid & 3) * 4;
    u64 acc[4][8] = {};                           // [m-pair][n]
    for (int k0 = 0; k0 < Kd; k0 += 16) {
#pragma unroll
        for (int r = 0; r < 2; r++) {
            int m = wm + r * 64;
            float4 wv = *(const float4*)(W + (size_t)(m0 + m) * Kd + k0 + wk);
            Wt[wk + 0][m] = wv.x; Wt[wk + 1][m] = wv.y;
            Wt[wk + 2][m] = wv.z; Wt[wk + 3][m] = wv.w;
        }
#pragma unroll
        for (int r = 0; r < 2; r++) {
            int idx = tid + r * 256;
            int k = idx >> 5, n4 = (idx & 31) * 4;
            *(float4*)(&As[k][n4]) = *(const float4*)(A + (size_t)(k0 + k) * N + n0 + n4);
        }
        __syncthreads();
#pragma unroll
        for (int k = 0; k < 16; k++) {
            ulonglong2 w01 = *(const ulonglong2*)(&Wt[k][tm * 8]);
            ulonglong2 w23 = *(const ulonglong2*)(&Wt[k][tm * 8 + 4]);
            float4 a0 = *(const float4*)(&As[k][tn * 8]);
            float4 a1 = *(const float4*)(&As[k][tn * 8 + 4]);
            u64 wp[4] = {w01.x, w01.y, w23.x, w23.y};
            u64 ad[8] = {pack2(a0.x, a0.x), pack2(a0.y, a0.y), pack2(a0.z, a0.z), pack2(a0.w, a0.w),
                         pack2(a1.x, a1.x), pack2(a1.y, a1.y), pack2(a1.z, a1.z), pack2(a1.w, a1.w)};
#pragma unroll
            for (int mp = 0; mp < 4; mp++)
#pragma unroll
                for (int j = 0; j < 8; j++)
                    ffma2(acc[mp][j], wp[mp], ad[j]);
        }
        __syncthreads();
    }
#pragma unroll
    for (int mp = 0; mp < 4; mp++) {
#pragma unroll
        for (int hh = 0; hh < 2; hh++) {
            int m = m0 + tm * 8 + mp * 2 + hh;
            float bv = bias[m];
            float v[8];
#pragma unroll
            for (int j = 0; j < 8; j++) {
                float2 p = unpack2(acc[mp][j]);
                v[j] = (hh ? p.y : p.x) + bv;
            }
            int n = n0 + tn * 8;
            if (ADD_POS) {
                if (m < 512) {
                    const float* pp = pos + (size_t)(m & 255) * N + n;
                    float4 p0 = *(const float4*)pp, p1 = *(const float4*)(pp + 4);
                    v[0] += p0.x; v[1] += p0.y; v[2] += p0.z; v[3] += p0.w;
                    v[4] += p1.x; v[5] += p1.y; v[6] += p1.z; v[7] += p1.w;
                }
            }
            float* cp = Cout + (size_t)m * N + n;
            *(float4*)cp       = make_float4(v[0], v[1], v[2], v[3]);
            *(float4*)(cp + 4) = make_float4(v[4], v[5], v[6], v[7]);
        }
    }
}

__global__ __launch_bounds__(256, 2)
void qkv_gemm_kernel(const float* __restrict__ pw_w, const float* __restrict__ dw,
                     const float* __restrict__ pw_b, const float* __restrict__ pos,
                     float* __restrict__ qkv) {
    int b = blockIdx.x;
    int i, N, bx, by, off, qoff;
    if (b < 192)      { i = 0; N = 4096; bx = b & 31;        by = b >> 5;        off = 0;    qoff = 0; }
    else if (b < 240) { i = 1; N = 1024; bx = (b - 192) & 7; by = (b - 192) >> 3; off = OFF2; qoff = QOFF2; }
    else              { i = 2; N = 256;  bx = (b - 240) & 1; by = (b - 240) >> 1; off = OFF4; qoff = QOFF4; }
    gemm_tile128<true>(pw_w + (size_t)i * 768 * 256, dw + off, pw_b + i * 768,
                       pos + off, qkv + qoff, 256, N, by * 128, bx * 128);
}

__global__ __launch_bounds__(256, 2)
void fusion_gemm_kernel(const float* __restrict__ fus_w, const float* __restrict__ cat,
                        const float* __restrict__ fus_b, float* __restrict__ out) {
    int b = blockIdx.x;
    gemm_tile128<false>(fus_w, cat, fus_b, nullptr, out, 3 * CC, NPIX,
                        (b >> 5) * 128, (b & 31) * 128);
}

// ---------------- flash attention: Q-tile 128, K-tile 64, 2 CTAs/SM ----------------
// QK: key-packed acc (Q dup via ALU). PV: m-packed acc — both operands natural pairs,
// zero packs, V natural (no transpose). S column-chunks XOR-swizzled by (row>>3)&1.
// smem: Qs[32][132] | Ks[2][32][68] | Vs[2][32][68] | S[128][68] = 86528 B (2 CTAs/SM)
__global__ __launch_bounds__(256, 2)
void attn_all_kernel(const float* __restrict__ qkv_base, float* __restrict__ cat,
                     float* __restrict__ att) {
    extern __shared__ float sm[];
    float (*Qs)[132]    = (float(*)[132])(sm);
    float (*Ks)[32][68] = (float(*)[32][68])(sm + 32 * 132);
    float (*Vs)[32][68] = (float(*)[32][68])(sm + 32 * 132 + 2 * 32 * 68);
    float (*S)[68]      = (float(*)[68])(sm + 32 * 132 + 4 * 32 * 68);

    int b = blockIdx.x;
    const float* qkv; float* out; int N, h, n0;
    if (b < 256)      { qkv = qkv_base;         out = cat;             N = 4096; h = b >> 5;        n0 = (b & 31) * 128; }
    else if (b < 320) { qkv = qkv_base + QOFF2; out = att;             N = 1024; h = (b - 256) >> 3; n0 = ((b - 256) & 7) * 128; }
    else              { qkv = qkv_base + QOFF4; out = att + CC * 1024; N = 256;  h = (b - 320) >> 1; n0 = ((b - 320) & 1) * 128; }

    int tid = threadIdx.x;
    const float scale = 0.17677669529663687f;    // 1/sqrt(32)
    const float* qb = qkv + (size_t)(h * 32) * N + n0;
    const float* kb = qkv + (size_t)(256 + h * 32) * N;
    const float* vb = qkv + (size_t)(512 + h * 32) * N;

    int rg = tid >> 3;          // 0..31: rows rg*4..+3 (warp w owns rows 16w..16w+15)
    int cg = tid & 7;           // QK: keys cg*8..+7 ; PV: dims cg+8k
    int swb = (rg >> 1) & 1;    // S chunk swizzle bit = (row>>3)&1

    // load Q tile 128x32, scaled
#pragma unroll
    for (int r = 0; r < 4; r++) {
        int idx = tid + r * 256;
        int d = idx >> 5, q4 = (idx & 31) * 4;
        float4 qv = *(const float4*)(qb + (size_t)d * N + q4);
        qv.x *= scale; qv.y *= scale; qv.z *= scale; qv.w *= scale;
        *(float4*)(&Qs[d][q4]) = qv;
    }

    float l_p[4] = {};
    u64 oacc[4][4] = {};        // [row i][dim k], lanes = (m-even, m-odd) partials

    int ld_d = tid >> 4, ld_m = (tid & 15) * 4;
    float4 kr[2], vr[2];
#pragma unroll
    for (int r = 0; r < 2; r++) {
        int d = ld_d + r * 16;
        kr[r] = *(const float4*)(kb + (size_t)d * N + ld_m);
        vr[r] = *(const float4*)(vb + (size_t)d * N + ld_m);
    }
#pragma unroll
    for (int r = 0; r < 2; r++) {
        int d = ld_d + r * 16;
        *(float4*)(&Ks[0][d][ld_m]) = kr[r];
        *(float4*)(&Vs[0][d][ld_m]) = vr[r];
    }
    __syncthreads();

    int T = N >> 6;
    for (int t = 0; t < T; t++) {
        int cur = t & 1;
        if (t + 1 < T) {
            int m0 = (t + 1) * 64;
#pragma unroll
            for (int r = 0; r < 2; r++) {
                int d = ld_d + r * 16;
                kr[r] = *(const float4*)(kb + (size_t)d * N + m0 + ld_m);
                vr[r] = *(const float4*)(vb + (size_t)d * N + m0 + ld_m);
            }
        }

        // ---- S = Q^T K : 4 rows x 8 keys, acc key-packed, Q dup via ALU ----
        u64 sacc[4][4] = {};
#pragma unroll
        for (int d = 0; d < 32; d++) {
            float4 qf = *(const float4*)(&Qs[d][rg * 4]);
            ulonglong2 k0 = *(const ulonglong2*)(&Ks[cur][d][cg * 8]);
            ulonglong2 k1 = *(const ulonglong2*)(&Ks[cur][d][cg * 8 + 4]);
            u64 q0 = pack2(qf.x, qf.x), q1 = pack2(qf.y, qf.y);
            u64 q2 = pack2(qf.z, qf.z), q3 = pack2(qf.w, qf.w);
            ffma2(sacc[0][0], q0, k0.x); ffma2(sacc[0][1], q0, k0.y);
            ffma2(sacc[0][2], q0, k1.x); ffma2(sacc[0][3], q0, k1.y);
            ffma2(sacc[1][0], q1, k0.x); ffma2(sacc[1][1], q1, k0.y);
            ffma2(sacc[1][2], q1, k1.x); ffma2(sacc[1][3], q1, k1.y);
            ffma2(sacc[2][0], q2, k0.x); ffma2(sacc[2][1], q2, k0.y);
            ffma2(sacc[2][2], q2, k1.x); ffma2(sacc[2][3], q2, k1.y);
            ffma2(sacc[3][0], q3, k0.x); ffma2(sacc[3][1], q3, k0.y);
            ffma2(sacc[3][2], q3, k1.x); ffma2(sacc[3][3], q3, k1.y);
        }

        // ---- exp (no max-sub: scores O(1), softmax shift-invariant) ----
#pragma unroll
        for (int i = 0; i < 4; i++) {
            float2 p0 = unpack2(sacc[i][0]), p1 = unpack2(sacc[i][1]);
            float2 p2 = unpack2(sacc[i][2]), p3 = unpack2(sacc[i][3]);
            float e0 = __expf(p0.x), e1 = __expf(p0.y), e2 = __expf(p1.x), e3 = __expf(p1.y);
            float e4 = __expf(p2.x), e5 = __expf(p2.y), e6 = __expf(p3.x), e7 = __expf(p3.y);
            l_p[i] += ((e0 + e1) + (e2 + e3)) + ((e4 + e5) + (e6 + e7));
            int row = rg * 4 + i;
            *(float4*)(&S[row][((cg * 2    ) ^ swb) * 4]) = make_float4(e0, e1, e2, e3);
            *(float4*)(&S[row][((cg * 2 + 1) ^ swb) * 4]) = make_float4(e4, e5, e6, e7);
        }
        __syncwarp();   // S rows 16w..16w+15 are warp-private

        // ---- O += P V^T : 4 rows x 4 dims (d = cg+8k), acc m-packed, zero dup ----
#pragma unroll
        for (int mc = 0; mc < 16; mc++) {
            ulonglong2 pp[4], vv[4];
#pragma unroll
            for (int i = 0; i < 4; i++)
                pp[i] = *(const ulonglong2*)(&S[rg * 4 + i][(mc ^ swb) * 4]);
#pragma unroll
            for (int k = 0; k < 4; k++)
                vv[k] = *(const ulonglong2*)(&Vs[cur][cg + 8 * k][mc * 4]);
#pragma unroll
            for (int i = 0; i < 4; i++)
#pragma unroll
                for (int k = 0; k < 4; k++) {
                    ffma2(oacc[i][k], pp[i].x, vv[k].x);
                    ffma2(oacc[i][k], pp[i].y, vv[k].y);
                }
        }

        if (t + 1 < T) {
#pragma unroll
            for (int r = 0; r < 2; r++) {
                int d = ld_d + r * 16;
                *(float4*)(&Ks[cur ^ 1][d][ld_m]) = kr[r];
                *(float4*)(&Vs[cur ^ 1][d][ld_m]) = vr[r];
            }
        }
        __syncthreads();
    }

    // reduce l over the 8 cg lanes (tid bits 0..2)
#pragma unroll
    for (int off = 1; off < 8; off <<= 1)
#pragma unroll
        for (int i = 0; i < 4; i++)
            l_p[i] += __shfl_xor_sync(0xffffffffu, l_p[i], off);
    float inv[4];
#pragma unroll
    for (int i = 0; i < 4; i++) inv[i] = 1.0f / l_p[i];

    // output: per dim k, horizontal-add the m-packed acc, one float4 over 4 rows
#pragma unroll
    for (int k = 0; k < 4; k++) {
        int d = cg + 8 * k;
        float o[4];
#pragma unroll
        for (int i = 0; i < 4; i++) {
            float2 p = unpack2(oacc[i][k]);
            o[i] = (p.x + p.y) * inv[i];
        }
        *(float4*)(out + (size_t)(h * 32 + d) * N + n0 + rg * 4) =
            make_float4(o[0], o[1], o[2], o[3]);
    }
}

// ---------------- bilinear upsample (jax.image.resize), both scales ----------------
__global__ void upsample_all_kernel(const float* __restrict__ att, float* __restrict__ cat) {
    int b = blockIdx.x;
    const float* in; float* dst; int s, Hs, idx;
    if (b < 4096) { in = att;             dst = cat + (size_t)CC * NPIX;     s = 2; Hs = 32; idx = b * 256 + threadIdx.x; }
    else          { in = att + CC * 1024; dst = cat + (size_t)2 * CC * NPIX; s = 4; Hs = 16; idx = (b - 4096) * 256 + threadIdx.x; }
    int xo = idx & 63, yo = (idx >> 6) & 63, c = idx >> 12;
    float fs = 1.0f / s;
    float fy = (yo + 0.5f) * fs - 0.5f;
    float fx = (xo + 0.5f) * fs - 0.5f;
    float fy0 = floorf(fy), fx0 = floorf(fx);
    float wy = fy - fy0, wx = fx - fx0;
    int y0 = (int)fy0, x0 = (int)fx0;
    int y0c = max(y0, 0), y1c = min(y0 + 1, Hs - 1);
    int x0c = max(x0, 0), x1c = min(x0 + 1, Hs - 1);
    const float* ip = in + (size_t)c * Hs * Hs;
    float v00 = ip[y0c * Hs + x0c], v01 = ip[y0c * Hs + x1c];
    float v10 = ip[y1c * Hs + x0c], v11 = ip[y1c * Hs + x1c];
    float v0 = v00 + (v01 - v00) * wx;
    float v1 = v10 + (v11 - v10) * wx;
    dst[idx] = v0 + (v1 - v0) * wy;
}

// ---------------- host launch ----------------
extern "C" void kernel_launch(void* const* d_in, const int* in_sizes, int n_in,
                              void* d_out, int out_size) {
    const float* x     = (const float*)d_in[0];
    const float* dw_w  = (const float*)d_in[1];
    const float* dw_b  = (const float*)d_in[2];
    const float* pw_w  = (const float*)d_in[3];
    const float* pw_b  = (const float*)d_in[4];
    const float* pos_w = (const float*)d_in[5];
    const float* pos_b = (const float*)d_in[6];
    const float* fus_w = (const float*)d_in[7];
    const float* fus_b = (const float*)d_in[8];
    float* out = (float*)d_out;

    static int attr_done = 0;
    if (!attr_done) {
        cudaFuncSetAttribute(attn_all_kernel, cudaFuncAttributeMaxDynamicSharedMemorySize, 86528);
        attr_done = 1;
    }

    float *xs, *dw, *pos, *qkv, *att, *cat;
    cudaGetSymbolAddress((void**)&xs,  g_xs);
    cudaGetSymbolAddress((void**)&dw,  g_dw);
    cudaGetSymbolAddress((void**)&pos, g_pos);
    cudaGetSymbolAddress((void**)&qkv, g_qkv);
    cudaGetSymbolAddress((void**)&att, g_att);
    cudaGetSymbolAddress((void**)&cat, g_cat);

    float* xs2 = xs;
    float* xs4 = xs + CC * 1024;

    pool_all_kernel  <<<1280, 256>>>(x, xs2, xs4);
    dwconv_all_kernel<<<5376, 256>>>(x, xs2, xs4, dw_w, dw_b, pos_w, pos_b, dw, pos);
    qkv_gemm_kernel  <<<252, 256>>>(pw_w, dw, pw_b, pos, qkv);
    attn_all_kernel  <<<336, 256, 86528>>>(qkv, cat, att);
    upsample_all_kernel<<<8192, 256>>>(att, cat);
    fusion_gemm_kernel<<<64, 256>>>(fus_w, cat, fus_b, out);
}